// round 7
// baseline (speedup 1.0000x reference)
#include <cuda_runtime.h>
#include <stdint.h>
#include <math.h>

#define NCAND  1600
#define NITER  100
#define NZ     16
#define NB     131072               // 2^17 bins
#define CHUNK  1024
#define NCHUNK (NB / CHUNK)         // 128
#define GRID   128
#define BLK    1024

#define CNT_SHIFT 42
#define SUM_MASK  ((1ull << CNT_SHIFT) - 1ull)
#define BIASI     ((s64)(1 << 18))

typedef unsigned long long u64;
typedef long long          s64;
typedef unsigned           u32;

// ---------------- device scratch ----------------
__device__ u32   g_ctr;             // barrier counter; reset to 0 by block 0 at end
__device__ float g_bmin[GRID], g_bmax[GRID];
__device__ u64   g_hist[NB];
__device__ u32   g_pc[NB + 1];      // chunk-relative exclusive prefix counts
__device__ u64   g_ps[NB + 1];      // chunk-relative exclusive prefix sums
__device__ u32   g_ccnt[NCHUNK];
__device__ u64   g_csum[NCHUNK];

// full barrier #k (k = 1,2): everyone arrives + spins
__device__ __forceinline__ void gbar_full(u32 k) {
    __syncthreads();
    if (threadIdx.x == 0) {
        __threadfence();
        atomicAdd(&g_ctr, 1u);
        u32 target = k * (u32)GRID;
        while ((int)(*(volatile u32*)&g_ctr - target) < 0) __nanosleep(64);
        __threadfence();
    }
    __syncthreads();
}

__global__ void __launch_bounds__(BLK, 1)
fused_kernel(const float4* __restrict__ x4, int n4, int ntot,
             float* __restrict__ out)
{
    const int tid  = threadIdx.x;
    const int bid  = blockIdx.x;
    const int gtid = bid * BLK + tid;          // < GRID*BLK == NB
    const int gsz  = GRID * BLK;

    __shared__ float  s_mn[32], s_mx[32];
    __shared__ float  s_rm[GRID], s_rx[GRID];
    __shared__ float  sb_xmin, sb_xmax, sb_invwf, sb_fixf;
    __shared__ s64    sb_cmin, sb_W;
    __shared__ int    sb_k;
    __shared__ u32    s_c[CHUNK];
    __shared__ u64    s_s[CHUNK];
    __shared__ u32    s_cc[NCHUNK];
    __shared__ u64    s_cs[NCHUNK];
    __shared__ u32    s_cpref[NCHUNK + 1];
    __shared__ u64    s_spref[NCHUNK + 1];
    __shared__ double s_score[NCAND];
    __shared__ float  s_nmin[NCAND], s_nmax[NCAND];
    __shared__ double sm_i[NITER];
    __shared__ int    j_i[NITER];

    // ---------------- P0: clear hist + per-block min/max ----------------
    g_hist[gtid] = 0ull;                       // NB == GRID*BLK, one each

    float lmin = 3.4e38f, lmax = -3.4e38f;
    for (int i = gtid; i < n4; i += gsz) {
        float4 v = __ldg(&x4[i]);
        lmin = fminf(lmin, fminf(fminf(v.x, v.y), fminf(v.z, v.w)));
        lmax = fmaxf(lmax, fmaxf(fmaxf(v.x, v.y), fmaxf(v.z, v.w)));
    }
    #pragma unroll
    for (int o = 16; o; o >>= 1) {
        lmin = fminf(lmin, __shfl_xor_sync(0xffffffffu, lmin, o));
        lmax = fmaxf(lmax, __shfl_xor_sync(0xffffffffu, lmax, o));
    }
    if ((tid & 31) == 0) { s_mn[tid >> 5] = lmin; s_mx[tid >> 5] = lmax; }
    __syncthreads();
    if (tid == 0) {
        #pragma unroll
        for (int i = 1; i < 32; i++) {
            lmin = fminf(lmin, s_mn[i]);
            lmax = fmaxf(lmax, s_mx[i]);
        }
        g_bmin[bid] = lmin;
        g_bmax[bid] = lmax;
    }
    gbar_full(1);

    // ---------------- P1: finish min/max, derive fixed-point params ------
    if (tid < GRID) {
        s_rm[tid] = __ldcg(&g_bmin[tid]);
        s_rx[tid] = __ldcg(&g_bmax[tid]);
    }
    __syncthreads();
    for (int off = GRID / 2; off; off >>= 1) {
        if (tid < off) {
            s_rm[tid] = fminf(s_rm[tid], s_rm[tid + off]);
            s_rx[tid] = fmaxf(s_rx[tid], s_rx[tid + off]);
        }
        __syncthreads();
    }
    if (tid == 0) {
        float xmin = s_rm[0], xmax = s_rx[0];
        float xr = xmax - xmin;
        float wbin = xr / (float)NB;
        int e2; frexpf(wbin, &e2);             // wbin = m*2^e2, m in [0.5,1)
        int K = 17 - e2;                       // W = wbin*2^K in [2^16, 2^17)
        float FIXF = ldexpf(1.0f, K);
        sb_xmin = xmin; sb_xmax = xmax;
        sb_invwf = (float)NB / xr;
        sb_fixf = FIXF;
        sb_W    = llrintf(wbin * FIXF);
        sb_cmin = llrintf(xmin * FIXF);
        sb_k    = K;
    }
    __syncthreads();
    const float xminf = sb_xmin;
    const float invwf = sb_invwf;
    const float FIXF  = sb_fixf;
    const s64   cmin  = sb_cmin;
    const s64   W     = sb_W;

    // ---------------- P1b: histogram (x now warm in L2) ------------------
    for (int i = gtid; i < n4; i += gsz) {
        float4 v = __ldg(&x4[i]);
        float f[4] = {v.x, v.y, v.z, v.w};
        #pragma unroll
        for (int k = 0; k < 4; k++) {
            int b = (int)((f[k] - xminf) * invwf);
            b = min(max(b, 0), NB - 1);
            s64 fx = llrintf(f[k] * FIXF) - cmin;
            u64 val = (1ull << CNT_SHIFT) + (u64)(fx - (s64)b * W + BIASI);
            atomicAdd(&g_hist[b], val);
        }
    }
    gbar_full(2);

    // ---------------- P2: chunk scan (block b <-> chunk b) ---------------
    {
        int i = bid * CHUNK + tid;
        u64 p = __ldcg(&g_hist[i]);
        u32 v = (u32)(p >> CNT_SHIFT);
        u64 w = (u64)((s64)(p & SUM_MASK) + (s64)v * ((s64)i * W - BIASI));
        s_c[tid] = v; s_s[tid] = w; __syncthreads();
        for (int off = 1; off < CHUNK; off <<= 1) {
            u32 a = 0; u64 a2 = 0;
            if (tid >= off) { a = s_c[tid - off]; a2 = s_s[tid - off]; }
            __syncthreads();
            s_c[tid] += a; s_s[tid] += a2;
            __syncthreads();
        }
        g_pc[i] = s_c[tid] - v;                // chunk-relative exclusive
        g_ps[i] = s_s[tid] - w;
        if (tid == CHUNK - 1) { g_ccnt[bid] = s_c[tid]; g_csum[bid] = s_s[tid]; }
        if (i == NB - 1) { g_pc[NB] = 0u; g_ps[NB] = 0ull; }
    }

    // ---------------- P3 sync: arrive-only for blocks != 0 ---------------
    __syncthreads();
    if (bid != 0) {
        if (tid == 0) { __threadfence(); atomicAdd(&g_ctr, 1u); }
        return;
    }
    if (tid == 0) {
        __threadfence();
        atomicAdd(&g_ctr, 1u);
        while ((int)(*(volatile u32*)&g_ctr - 3u * GRID) < 0) __nanosleep(64);
        __threadfence();
    }
    __syncthreads();

    // ---------------- P4 (block 0): scores + reference-exact select ------
    if (tid < NCHUNK) {
        s_cc[tid] = __ldcg(&g_ccnt[tid]);
        s_cs[tid] = __ldcg(&g_csum[tid]);
    }
    __syncthreads();
    if (tid <= NCHUNK) {
        u32 c = 0; u64 s = 0;
        for (int j = 0; j < tid; j++) { c += s_cc[j]; s += s_cs[j]; }
        s_cpref[tid] = c; s_spref[tid] = s;
    }
    __syncthreads();

    const float x_min = sb_xmin;
    const float x_max = sb_xmax;
    const float xrange = x_max - x_min;
    const double cmind = (double)cmin;
    const double INVF  = ldexp(1.0, -sb_k);
    const float EPS = 1.1920929e-7f;           // np.finfo(float32).eps

    for (int c = tid; c < NCAND; c += BLK) {
        int ii = c / NZ + 1;
        int z  = c % NZ;
        float fi = (float)ii, fz = (float)z;
        float tmp_max   = xrange / 100.0f * fi;
        float tmp_delta = tmp_max / 15.0f;
        float new_min = fmaxf(-fz * tmp_delta, x_min);
        float new_max = fminf(tmp_max - fz * tmp_delta, x_max);
        float min_neg = fminf(new_min, 0.0f);
        float max_pos = fmaxf(new_max, 0.0f);
        float scale = fmaxf((max_pos - min_neg) / 15.0f, EPS);
        float zp = fminf(fmaxf(0.0f - rintf(min_neg / scale), 0.0f), 15.0f);
        float ql = -zp;
        s_nmin[c] = new_min;
        s_nmax[c] = new_max;

        int e[NZ + 1];
        e[0] = 0; e[NZ] = NB;
        #pragma unroll
        for (int m = 0; m < NZ - 1; m++) {
            float t = ((ql + (float)m + 0.5f) * scale - xminf) * invwf;
            int ei;
            if (!(t > 0.0f))            ei = 0;
            else if (t >= (float)NB)    ei = NB;
            else                        ei = (int)t;
            e[m + 1] = ei;
        }
        #pragma unroll
        for (int m = 1; m < NZ; m++) if (e[m] < e[m - 1]) e[m] = e[m - 1];

        double num = 0.0;
        #pragma unroll
        for (int m = 0; m < NZ; m++) {
            int e0 = e[m], e1 = e[m + 1];
            u32 pc0 = s_cpref[e0 >> 10] + __ldcg(&g_pc[e0]);
            u32 pc1 = s_cpref[e1 >> 10] + __ldcg(&g_pc[e1]);
            u64 ps0 = s_spref[e0 >> 10] + __ldcg(&g_ps[e0]);
            u64 ps1 = s_spref[e1 >> 10] + __ldcg(&g_ps[e1]);
            double Nm = (double)(pc1 - pc0);
            double S1 = ((double)(s64)(ps1 - ps0) + Nm * cmind) * INVF;
            float a = (ql + (float)m) * scale;
            double ad = (double)a;
            num += ad * ad * Nm - 2.0 * ad * S1;
        }
        s_score[c] = num / (double)ntot;       // Σx² omitted: constant offset
    }
    __syncthreads();

    if (tid < NITER) {
        int j = 0;
        double sm = s_score[tid * NZ];
        #pragma unroll
        for (int z = 1; z < NZ; z++) {
            double s = s_score[tid * NZ + z];
            if (s < sm) { sm = s; j = z; }     // first-occurrence argmin
        }
        sm_i[tid] = sm; j_i[tid] = j;
    }
    __syncthreads();
    if (tid == 0) {
        double best = 1e30;
        float bmin = x_min, bmax = x_max;
        for (int i = 0; i < NITER; i++) {
            if (sm_i[i] < best) {              // strict <, like reference
                best = sm_i[i];
                bmin = s_nmin[i * NZ + j_i[i]];
                bmax = s_nmax[i * NZ + j_i[i]];
            }
        }
        out[0] = bmin;
        out[1] = bmax;
        atomicExch(&g_ctr, 0u);                // reset barrier for next replay
    }
}

extern "C" void kernel_launch(void* const* d_in, const int* in_sizes, int n_in,
                              void* d_out, int out_size) {
    const float* x = (const float*)d_in[0];
    int n = in_sizes[0];
    fused_kernel<<<GRID, BLK>>>((const float4*)x, n / 4, n, (float*)d_out);
}